// round 2
// baseline (speedup 1.0000x reference)
#include <cuda_runtime.h>

#define BATCH 256
#define TSTEPS 250
#define NIN 700
#define NHID 512
#define NOUT 20
#define KTOT (4*NIN)        // 2800
#define MROWS (BATCH*TSTEPS)  // 64000

// ---------------- scratch (device globals: no allocations allowed) ----------
__device__ float g_iin[(size_t)MROWS * NHID];     // 131 MB: i_in[b*T+t][h]
__device__ float g_wT[(size_t)KTOT * NHID];       // concat-transposed weights [kk][h]
__device__ float g_wrecT[(size_t)NHID * NHID];    // w_rec^T [j][h]

// ---------------- prep kernels ----------------------------------------------
__global__ void prep_weights(const float* __restrict__ wkan,
                             const float* __restrict__ d1,
                             const float* __restrict__ d2,
                             const float* __restrict__ d3) {
    int idx = blockIdx.x * blockDim.x + threadIdx.x;
    if (idx >= KTOT * NHID) return;
    int kk = idx / NHID;
    int h  = idx - kk * NHID;
    int v  = kk / NIN;
    int k  = kk - v * NIN;
    const float* w = (v == 0) ? wkan : (v == 1) ? d1 : (v == 2) ? d2 : d3;
    g_wT[idx] = w[h * NIN + k];
}

__global__ void prep_wrec(const float* __restrict__ wrec) {
    int idx = blockIdx.x * blockDim.x + threadIdx.x;
    if (idx >= NHID * NHID) return;
    int j = idx / NHID;
    int h = idx - j * NHID;
    g_wrecT[idx] = wrec[h * NHID + j];
}

// ---------------- phase 1: i_in GEMM (fp32, classic 128x128x8 tile) ---------
#define BM 128
#define BN 128
#define BK 8
#define TM 8
#define TN 8

__global__ void __launch_bounds__(256) gemm_iin(const float* __restrict__ x) {
    __shared__ float As[BK][BM];
    __shared__ float Bs[BK][BN];

    const int bn = blockIdx.x;      // 0..3
    const int bm = blockIdx.y;      // 0..499
    const int tid = threadIdx.x;

    const int trow = tid / 16;      // 0..15, covers TM*16 = 128 rows
    const int tcol = tid % 16;      // 0..15, covers TN*16 = 128 cols

    const int m0 = bm * BM;
    const int n0 = bn * BN;

    // A-load mapping: 128 rows x 8 k -> 4 scalars/thread
    const int a_row = tid >> 1;           // 0..127
    const int a_k0  = (tid & 1) * 4;      // 0 or 4
    // B-load mapping: 8 k x 128 n -> 1 float4/thread
    const int b_k  = tid >> 5;            // 0..7
    const int b_n4 = (tid & 31) * 4;      // 0..124

    float acc[TM][TN];
#pragma unroll
    for (int i = 0; i < TM; i++)
#pragma unroll
        for (int j = 0; j < TN; j++) acc[i][j] = 0.f;

    const float* xrow = x + (size_t)(m0 + a_row) * NIN;

    for (int kk0 = 0; kk0 < KTOT; kk0 += BK) {
        // load + transform A
#pragma unroll
        for (int i = 0; i < 4; i++) {
            int kk = kk0 + a_k0 + i;
            int v = kk / NIN;
            int k = kk - v * NIN;
            float a = __ldg(&xrow[k]);
            float t1 = fminf(fabsf(a), 1.0f);
            float val;
            if (v == 0)      val = a;
            else if (v == 1) val = t1;
            else if (v == 2) val = t1 * t1;
            else             val = t1 * t1 * t1;
            As[a_k0 + i][a_row] = val;
        }
        // load B
        float4 bv = *(const float4*)(&g_wT[(size_t)(kk0 + b_k) * NHID + n0 + b_n4]);
        *(float4*)(&Bs[b_k][b_n4]) = bv;
        __syncthreads();

#pragma unroll
        for (int k = 0; k < BK; k++) {
            float ar[TM], br[TN];
#pragma unroll
            for (int i = 0; i < TM; i++) ar[i] = As[k][trow * TM + i];
#pragma unroll
            for (int j = 0; j < TN; j++) br[j] = Bs[k][tcol * TN + j];
#pragma unroll
            for (int i = 0; i < TM; i++)
#pragma unroll
                for (int j = 0; j < TN; j++)
                    acc[i][j] = fmaf(ar[i], br[j], acc[i][j]);
        }
        __syncthreads();
    }

#pragma unroll
    for (int i = 0; i < TM; i++) {
        int m = m0 + trow * TM + i;
        float* crow = &g_iin[(size_t)m * NHID + n0 + tcol * TN];
#pragma unroll
        for (int j = 0; j < TN; j += 4) {
            float4 o = make_float4(acc[i][j], acc[i][j+1], acc[i][j+2], acc[i][j+3]);
            *(float4*)(crow + j) = o;
        }
    }
}

// ---------------- phase 2: persistent per-batch recurrence ------------------
// 256 blocks (one per batch element), 512 threads (one per hidden neuron).
__global__ void __launch_bounds__(512) snn_seq(const float* __restrict__ wout,
                                               float* __restrict__ out) {
    __shared__ float s_wout[NOUT * NHID];   // 40 KB
    __shared__ float s_sf[NHID];            // spike flags (float 0/1)
    __shared__ int   s_list[NHID];          // spike index list (prev step)
    __shared__ int   s_warpcnt[16];
    __shared__ int   s_cnt;
    __shared__ float s_iout[NOUT];

    const int b = blockIdx.x;
    const int h = threadIdx.x;
    const int warp = h >> 5;
    const int lane = h & 31;

    for (int i = h; i < NOUT * NHID; i += 512) s_wout[i] = wout[i];
    s_sf[h] = 0.f;
    if (h == 0) s_cnt = 0;

    float v1 = 0.f, a1 = 0.f, s_prev = 0.f;
    float v_out = 0.f, acc_out = 0.f;   // only meaningful for h < NOUT

    __syncthreads();

    const float* iin_b = &g_iin[(size_t)b * TSTEPS * NHID];

    for (int t = 0; t < TSTEPS; t++) {
        // ---- recurrent input via spike-list gather (prev-step s1) ----
        float rec = 0.f;
        const int cnt = s_cnt;
        int k = 0;
        for (; k + 4 <= cnt; k += 4) {
            int j0 = s_list[k], j1 = s_list[k+1], j2 = s_list[k+2], j3 = s_list[k+3];
            float w0 = g_wrecT[(size_t)j0 * NHID + h];
            float w1 = g_wrecT[(size_t)j1 * NHID + h];
            float w2 = g_wrecT[(size_t)j2 * NHID + h];
            float w3 = g_wrecT[(size_t)j3 * NHID + h];
            rec += w0 + w1 + w2 + w3;
        }
        for (; k < cnt; k++) rec += g_wrecT[(size_t)s_list[k] * NHID + h];

        const float i1 = iin_b[(size_t)t * NHID + h] + rec;

        // ---- adaptive LIF (uses PREVIOUS spike) ----
        v1 = 0.95f * v1 + 0.05f * i1 - 1.0f * s_prev;
        a1 = 0.85f * a1 + 0.15f * s_prev;
        const float thr = 1.0f + 0.05f * a1;
        const float s_new = (v1 > thr) ? 1.f : 0.f;

        const unsigned mask = __ballot_sync(0xffffffffu, s_new > 0.f);

        __syncthreads();   // A: everyone done reading old s_list / s_cnt

        if (lane == 0) s_warpcnt[warp] = __popc(mask);
        s_sf[h] = s_new;

        __syncthreads();   // B: warpcnt + s_sf visible

        // build new spike list
        int base = 0;
#pragma unroll
        for (int w = 0; w < 16; w++) base += (w < warp) ? s_warpcnt[w] : 0;
        if (s_new > 0.f) {
            int pos = base + __popc(mask & ((1u << lane) - 1u));
            s_list[pos] = h;
        }
        if (h == 0) {
            int tot = 0;
#pragma unroll
            for (int w = 0; w < 16; w++) tot += s_warpcnt[w];
            s_cnt = tot;
        }

        // ---- readout: i_out[o] = sum_h s_new[h]*w_out[o,h] (dense warp reduce)
        for (int o = warp; o < NOUT; o += 16) {
            float p = 0.f;
            const float* wrow = &s_wout[o * NHID];
#pragma unroll 4
            for (int i = lane; i < NHID; i += 32) p += s_sf[i] * wrow[i];
#pragma unroll
            for (int off = 16; off > 0; off >>= 1)
                p += __shfl_down_sync(0xffffffffu, p, off);
            if (lane == 0) s_iout[o] = p;
        }

        __syncthreads();   // C: s_iout + new s_list/s_cnt visible

        if (h < NOUT) {
            v_out = 0.9f * v_out + s_iout[h];
            const float s_o = (v_out > 1.0f) ? 1.f : 0.f;
            v_out = v_out - 1.0f * s_o;
            acc_out += v_out;
        }

        s_prev = s_new;
    }

    if (h < NOUT) out[b * NOUT + h] = acc_out * (1.0f / (float)TSTEPS);
}

// ---------------- launch -----------------------------------------------------
extern "C" void kernel_launch(void* const* d_in, const int* in_sizes, int n_in,
                              void* d_out, int out_size) {
    const float* x    = (const float*)d_in[0];
    const float* wkan = (const float*)d_in[1];
    const float* d1   = (const float*)d_in[2];
    const float* d2   = (const float*)d_in[3];
    const float* d3   = (const float*)d_in[4];
    const float* wrec = (const float*)d_in[5];
    const float* wout = (const float*)d_in[6];
    float* out = (float*)d_out;

    prep_weights<<<(KTOT * NHID + 255) / 256, 256>>>(wkan, d1, d2, d3);
    prep_wrec<<<(NHID * NHID + 255) / 256, 256>>>(wrec);

    dim3 grid(NHID / BN, MROWS / BM);   // (4, 500)
    gemm_iin<<<grid, 256>>>(x);

    snn_seq<<<BATCH, 512>>>(wout, out);
}

// round 4
// speedup vs baseline: 1.5503x; 1.5503x over previous
#include <cuda_runtime.h>
#include <cstdint>

#define BATCH 256
#define TSTEPS 250
#define NIN 700
#define NHID 512
#define NOUT 20
#define VPITCH 704            // per-variant padded K
#define KPAD (4*VPITCH)       // 2816
#define MROWS (BATCH*TSTEPS)  // 64000

// ---------------- device scratch (no allocations allowed) -------------------
__device__ float g_iin[(size_t)MROWS * NHID];
__device__ float g_wrecT[(size_t)NHID * NHID];
__device__ float g_Ahi[(size_t)MROWS * KPAD];
__device__ float g_Alo[(size_t)MROWS * KPAD];
__device__ float g_Bhi[(size_t)NHID * KPAD];
__device__ float g_Blo[(size_t)NHID * KPAD];

__device__ __forceinline__ float tf32r(float x) {
    float r;
    asm("cvt.rna.tf32.f32 %0, %1;" : "=f"(r) : "f"(x));
    return r;
}

// ---------------- prep kernels ----------------------------------------------
// A: transformed x, split into tf32 hi/lo. Each thread: one (m, k4) -> 4 variants.
__global__ void prep_A(const float* __restrict__ x) {
    int idx = blockIdx.x * blockDim.x + threadIdx.x;      // over MROWS * 176
    if (idx >= MROWS * (VPITCH / 4)) return;
    int m = idx / (VPITCH / 4);
    int k = (idx % (VPITCH / 4)) * 4;
    const float* xr = x + (size_t)m * NIN;
    float a[4];
#pragma unroll
    for (int j = 0; j < 4; j++) a[j] = (k + j < NIN) ? xr[k + j] : 0.f;

    size_t base = (size_t)m * KPAD + k;
#pragma unroll
    for (int v = 0; v < 4; v++) {
        float hi4[4], lo4[4];
#pragma unroll
        for (int j = 0; j < 4; j++) {
            float t1 = fminf(fabsf(a[j]), 1.f);
            float val = (v == 0) ? a[j] : (v == 1) ? t1 : (v == 2) ? t1 * t1 : t1 * t1 * t1;
            float h = tf32r(val);
            hi4[j] = h;
            lo4[j] = tf32r(val - h);
        }
        *(float4*)&g_Ahi[base + (size_t)v * VPITCH] = make_float4(hi4[0], hi4[1], hi4[2], hi4[3]);
        *(float4*)&g_Alo[base + (size_t)v * VPITCH] = make_float4(lo4[0], lo4[1], lo4[2], lo4[3]);
    }
}

__global__ void prep_B(const float* __restrict__ wkan, const float* __restrict__ d1,
                       const float* __restrict__ d2, const float* __restrict__ d3) {
    int idx = blockIdx.x * blockDim.x + threadIdx.x;      // over NHID * 176
    if (idx >= NHID * (VPITCH / 4)) return;
    int h = idx / (VPITCH / 4);
    int k = (idx % (VPITCH / 4)) * 4;
    size_t base = (size_t)h * KPAD + k;
#pragma unroll
    for (int v = 0; v < 4; v++) {
        const float* w = (v == 0) ? wkan : (v == 1) ? d1 : (v == 2) ? d2 : d3;
        float hi4[4], lo4[4];
#pragma unroll
        for (int j = 0; j < 4; j++) {
            float val = (k + j < NIN) ? w[h * NIN + k + j] : 0.f;
            float hh = tf32r(val);
            hi4[j] = hh;
            lo4[j] = tf32r(val - hh);
        }
        *(float4*)&g_Bhi[base + (size_t)v * VPITCH] = make_float4(hi4[0], hi4[1], hi4[2], hi4[3]);
        *(float4*)&g_Blo[base + (size_t)v * VPITCH] = make_float4(lo4[0], lo4[1], lo4[2], lo4[3]);
    }
}

__global__ void prep_wrec(const float* __restrict__ wrec) {
    int idx = blockIdx.x * blockDim.x + threadIdx.x;
    if (idx >= NHID * NHID) return;
    int j = idx / NHID;
    int h = idx - j * NHID;
    g_wrecT[idx] = wrec[h * NHID + j];
}

// ---------------- phase 1: mma.sync tf32x3 GEMM -----------------------------
// C[64000,512] = Ahi Bhi^T + Ahi Blo^T + Alo Bhi^T
#define BM 128
#define BN 128
#define KC 32
#define NCHUNK (KPAD / KC)     // 88
#define APITCH 36              // floats per smem row (conflict-free for frag LDS)
#define ARR (128 * APITCH)     // 4608 floats per array
#define STGF (4 * ARR)         // 18432 floats per stage
#define SMEM_BYTES (2 * STGF * 4)  // 147456

// offsets (in floats) within a stage
#define O_AHI 0
#define O_ALO ARR
#define O_BHI (2 * ARR)
#define O_BLO (3 * ARR)

__device__ __forceinline__ uint32_t smem_u32(const void* p) {
    uint32_t a;
    asm("{ .reg .u64 t; cvta.to.shared.u64 t, %1; cvt.u32.u64 %0, t; }" : "=r"(a) : "l"(p));
    return a;
}
__device__ __forceinline__ void cpa16(uint32_t s, const float* g) {
    asm volatile("cp.async.cg.shared.global [%0], [%1], 16;" :: "r"(s), "l"(g));
}

#define MMA_TF32(C, A, B) \
    asm volatile("mma.sync.aligned.m16n8k8.row.col.f32.tf32.tf32.f32 " \
                 "{%0,%1,%2,%3}, {%4,%5,%6,%7}, {%8,%9}, {%0,%1,%2,%3};" \
                 : "+f"((C)[0]), "+f"((C)[1]), "+f"((C)[2]), "+f"((C)[3]) \
                 : "r"((A)[0]), "r"((A)[1]), "r"((A)[2]), "r"((A)[3]), \
                   "r"((B)[0]), "r"((B)[1]))

__global__ void __launch_bounds__(256, 1) gemm_mma() {
    extern __shared__ float sm[];
    const uint32_t sb = smem_u32(sm);
    const int tid = threadIdx.x;
    const int warp = tid >> 5;
    const int lane = tid & 31;
    const int wm = (warp >> 2) * 64;      // warp M offset (0 / 64)
    const int wn = (warp & 3) * 32;       // warp N offset (0/32/64/96)
    const int m0 = blockIdx.y * BM;
    const int n0 = blockIdx.x * BN;

    float acc[4][4][4];
#pragma unroll
    for (int i = 0; i < 4; i++)
#pragma unroll
        for (int j = 0; j < 4; j++)
#pragma unroll
            for (int q = 0; q < 4; q++) acc[i][j][q] = 0.f;

    // per-thread copy mapping: 4 float4 per array; i = tid + it*256; r=i>>3, c=i&7
    const int cr = tid >> 3;              // base row (advances by 32 per it)
    const int cc = (tid & 7) * 4;         // float offset within 32-float row

    // ---- prologue: stage 0 = chunk 0 ----
    {
        uint32_t s0 = sb;
#pragma unroll
        for (int it = 0; it < 4; it++) {
            int r = cr + it * 32;
            uint32_t so = (uint32_t)(r * APITCH + cc) * 4;
            size_t ga = (size_t)(m0 + r) * KPAD + cc;
            size_t gb = (size_t)(n0 + r) * KPAD + cc;
            cpa16(s0 + O_AHI * 4 + so, &g_Ahi[ga]);
            cpa16(s0 + O_ALO * 4 + so, &g_Alo[ga]);
            cpa16(s0 + O_BHI * 4 + so, &g_Bhi[gb]);
            cpa16(s0 + O_BLO * 4 + so, &g_Blo[gb]);
        }
        asm volatile("cp.async.commit_group;" ::: "memory");
    }

    for (int ch = 0; ch < NCHUNK; ch++) {
        if (ch + 1 < NCHUNK) {
            uint32_t s1 = sb + ((ch + 1) & 1) * (STGF * 4);
            int kk0 = (ch + 1) * KC;
#pragma unroll
            for (int it = 0; it < 4; it++) {
                int r = cr + it * 32;
                uint32_t so = (uint32_t)(r * APITCH + cc) * 4;
                size_t ga = (size_t)(m0 + r) * KPAD + kk0 + cc;
                size_t gb = (size_t)(n0 + r) * KPAD + kk0 + cc;
                cpa16(s1 + O_AHI * 4 + so, &g_Ahi[ga]);
                cpa16(s1 + O_ALO * 4 + so, &g_Alo[ga]);
                cpa16(s1 + O_BHI * 4 + so, &g_Bhi[gb]);
                cpa16(s1 + O_BLO * 4 + so, &g_Blo[gb]);
            }
            asm volatile("cp.async.commit_group;" ::: "memory");
            asm volatile("cp.async.wait_group 1;" ::: "memory");
        } else {
            asm volatile("cp.async.wait_group 0;" ::: "memory");
        }
        __syncthreads();

        const uint32_t* S = (const uint32_t*)(sm + (ch & 1) * STGF);

#pragma unroll
        for (int ks = 0; ks < 4; ks++) {
            const int k0 = ks * 8;
            uint32_t ahi[4][4], alo[4][4], bhi[4][2], blo[4][2];
            const int rA = wm + (lane >> 2);
            const int cA = k0 + (lane & 3);
#pragma unroll
            for (int i = 0; i < 4; i++) {
                int r = rA + i * 16;
                ahi[i][0] = S[O_AHI + r * APITCH + cA];
                ahi[i][1] = S[O_AHI + (r + 8) * APITCH + cA];
                ahi[i][2] = S[O_AHI + r * APITCH + cA + 4];
                ahi[i][3] = S[O_AHI + (r + 8) * APITCH + cA + 4];
                alo[i][0] = S[O_ALO + r * APITCH + cA];
                alo[i][1] = S[O_ALO + (r + 8) * APITCH + cA];
                alo[i][2] = S[O_ALO + r * APITCH + cA + 4];
                alo[i][3] = S[O_ALO + (r + 8) * APITCH + cA + 4];
            }
            const int nB = wn + (lane >> 2);
            const int kB = k0 + (lane & 3);
#pragma unroll
            for (int j = 0; j < 4; j++) {
                int n = nB + j * 8;
                bhi[j][0] = S[O_BHI + n * APITCH + kB];
                bhi[j][1] = S[O_BHI + n * APITCH + kB + 4];
                blo[j][0] = S[O_BLO + n * APITCH + kB];
                blo[j][1] = S[O_BLO + n * APITCH + kB + 4];
            }
#pragma unroll
            for (int i = 0; i < 4; i++)
#pragma unroll
                for (int j = 0; j < 4; j++) MMA_TF32(acc[i][j], ahi[i], bhi[j]);
#pragma unroll
            for (int i = 0; i < 4; i++)
#pragma unroll
                for (int j = 0; j < 4; j++) MMA_TF32(acc[i][j], ahi[i], blo[j]);
#pragma unroll
            for (int i = 0; i < 4; i++)
#pragma unroll
                for (int j = 0; j < 4; j++) MMA_TF32(acc[i][j], alo[i], bhi[j]);
        }
        __syncthreads();
    }

    // ---- epilogue: frags -> smem bounce -> coalesced gmem ----
    {
        float* sC = sm;                    // [128][132]
#pragma unroll
        for (int i = 0; i < 4; i++) {
            int r = wm + i * 16 + (lane >> 2);
#pragma unroll
            for (int j = 0; j < 4; j++) {
                int c = wn + j * 8 + 2 * (lane & 3);
                sC[r * 132 + c]       = acc[i][j][0];
                sC[r * 132 + c + 1]   = acc[i][j][1];
                sC[(r + 8) * 132 + c]     = acc[i][j][2];
                sC[(r + 8) * 132 + c + 1] = acc[i][j][3];
            }
        }
        __syncthreads();
#pragma unroll
        for (int it = 0; it < 16; it++) {
            int i = tid + it * 256;        // 0..4095 float4s
            int r = i >> 5, c4 = (i & 31) * 4;
            float4 v = *(float4*)&sC[r * 132 + c4];
            *(float4*)&g_iin[(size_t)(m0 + r) * NHID + n0 + c4] = v;
        }
    }
}

// ---------------- phase 2: persistent per-batch recurrence ------------------
__global__ void __launch_bounds__(512) snn_seq(const float* __restrict__ wout,
                                               float* __restrict__ out) {
    __shared__ float s_wout[NOUT * NHID];
    __shared__ float s_sf[NHID];
    __shared__ int   s_list[NHID];
    __shared__ int   s_warpcnt[16];
    __shared__ int   s_cnt;
    __shared__ float s_iout[NOUT];

    const int b = blockIdx.x;
    const int h = threadIdx.x;
    const int warp = h >> 5;
    const int lane = h & 31;

    for (int i = h; i < NOUT * NHID; i += 512) s_wout[i] = wout[i];
    s_sf[h] = 0.f;
    if (h == 0) s_cnt = 0;

    float v1 = 0.f, a1 = 0.f, s_prev = 0.f;
    float v_out = 0.f, acc_out = 0.f;

    __syncthreads();

    const float* iin_b = &g_iin[(size_t)b * TSTEPS * NHID];

    for (int t = 0; t < TSTEPS; t++) {
        float rec = 0.f;
        const int cnt = s_cnt;
        int k = 0;
        for (; k + 4 <= cnt; k += 4) {
            int j0 = s_list[k], j1 = s_list[k + 1], j2 = s_list[k + 2], j3 = s_list[k + 3];
            float w0 = g_wrecT[(size_t)j0 * NHID + h];
            float w1 = g_wrecT[(size_t)j1 * NHID + h];
            float w2 = g_wrecT[(size_t)j2 * NHID + h];
            float w3 = g_wrecT[(size_t)j3 * NHID + h];
            rec += w0 + w1 + w2 + w3;
        }
        for (; k < cnt; k++) rec += g_wrecT[(size_t)s_list[k] * NHID + h];

        const float i1 = iin_b[(size_t)t * NHID + h] + rec;

        v1 = 0.95f * v1 + 0.05f * i1 - 1.0f * s_prev;
        a1 = 0.85f * a1 + 0.15f * s_prev;
        const float thr = 1.0f + 0.05f * a1;
        const float s_new = (v1 > thr) ? 1.f : 0.f;

        const unsigned mask = __ballot_sync(0xffffffffu, s_new > 0.f);

        __syncthreads();

        if (lane == 0) s_warpcnt[warp] = __popc(mask);
        s_sf[h] = s_new;

        __syncthreads();

        int base = 0;
#pragma unroll
        for (int w = 0; w < 16; w++) base += (w < warp) ? s_warpcnt[w] : 0;
        if (s_new > 0.f) {
            int pos = base + __popc(mask & ((1u << lane) - 1u));
            s_list[pos] = h;
        }
        if (h == 0) {
            int tot = 0;
#pragma unroll
            for (int w = 0; w < 16; w++) tot += s_warpcnt[w];
            s_cnt = tot;
        }

        for (int o = warp; o < NOUT; o += 16) {
            float p = 0.f;
            const float* wrow = &s_wout[o * NHID];
#pragma unroll 4
            for (int i = lane; i < NHID; i += 32) p += s_sf[i] * wrow[i];
#pragma unroll
            for (int off = 16; off > 0; off >>= 1)
                p += __shfl_down_sync(0xffffffffu, p, off);
            if (lane == 0) s_iout[o] = p;
        }

        __syncthreads();

        if (h < NOUT) {
            v_out = 0.9f * v_out + s_iout[h];
            const float s_o = (v_out > 1.0f) ? 1.f : 0.f;
            v_out = v_out - 1.0f * s_o;
            acc_out += v_out;
        }

        s_prev = s_new;
    }

    if (h < NOUT) out[b * NOUT + h] = acc_out * (1.0f / (float)TSTEPS);
}

// ---------------- launch -----------------------------------------------------
extern "C" void kernel_launch(void* const* d_in, const int* in_sizes, int n_in,
                              void* d_out, int out_size) {
    const float* x    = (const float*)d_in[0];
    const float* wkan = (const float*)d_in[1];
    const float* d1   = (const float*)d_in[2];
    const float* d2   = (const float*)d_in[3];
    const float* d3   = (const float*)d_in[4];
    const float* wrec = (const float*)d_in[5];
    const float* wout = (const float*)d_in[6];
    float* out = (float*)d_out;

    cudaFuncSetAttribute(gemm_mma, cudaFuncAttributeMaxDynamicSharedMemorySize, SMEM_BYTES);

    prep_A<<<(MROWS * (VPITCH / 4) + 255) / 256, 256>>>(x);
    prep_B<<<(NHID * (VPITCH / 4) + 255) / 256, 256>>>(wkan, d1, d2, d3);
    prep_wrec<<<(NHID * NHID + 255) / 256, 256>>>(wrec);

    dim3 grid(NHID / BN, MROWS / BM);   // (4, 500)
    gemm_mma<<<grid, 256, SMEM_BYTES>>>();

    snn_seq<<<BATCH, 512>>>(wout, out);
}

// round 5
// speedup vs baseline: 2.4679x; 1.5919x over previous
#include <cuda_runtime.h>
#include <cuda_bf16.h>
#include <cstdint>

#define BATCH 256
#define TSTEPS 250
#define NIN 700
#define NHID 512
#define NOUT 20
#define VPITCH 704            // per-variant padded K
#define KPAD (4*VPITCH)       // 2816
#define MROWS (BATCH*TSTEPS)  // 64000

// ---------------- device scratch (no allocations allowed) -------------------
__device__ float g_iin[(size_t)MROWS * NHID];
__device__ float g_wrecT[(size_t)NHID * NHID];
__device__ __nv_bfloat16 g_Ahi[(size_t)MROWS * KPAD];
__device__ __nv_bfloat16 g_Alo[(size_t)MROWS * KPAD];
__device__ __nv_bfloat16 g_Bhi[(size_t)NHID * KPAD];
__device__ __nv_bfloat16 g_Blo[(size_t)NHID * KPAD];

// ---------------- prep kernels ----------------------------------------------
__global__ void prep_A(const float* __restrict__ x) {
    int idx = blockIdx.x * blockDim.x + threadIdx.x;      // over MROWS * 176
    if (idx >= MROWS * (VPITCH / 4)) return;
    int m = idx / (VPITCH / 4);
    int k = (idx % (VPITCH / 4)) * 4;
    const float* xr = x + (size_t)m * NIN;
    float a[4];
#pragma unroll
    for (int j = 0; j < 4; j++) a[j] = (k + j < NIN) ? xr[k + j] : 0.f;

    size_t base = (size_t)m * KPAD + k;
#pragma unroll
    for (int v = 0; v < 4; v++) {
        union { __nv_bfloat16 b[4]; uint2 u; } ph, pl;
#pragma unroll
        for (int j = 0; j < 4; j++) {
            float t1 = fminf(fabsf(a[j]), 1.f);
            float val = (v == 0) ? a[j] : (v == 1) ? t1 : (v == 2) ? t1 * t1 : t1 * t1 * t1;
            __nv_bfloat16 h = __float2bfloat16_rn(val);
            ph.b[j] = h;
            pl.b[j] = __float2bfloat16_rn(val - __bfloat162float(h));
        }
        *(uint2*)&g_Ahi[base + (size_t)v * VPITCH] = ph.u;
        *(uint2*)&g_Alo[base + (size_t)v * VPITCH] = pl.u;
    }
}

__global__ void prep_B(const float* __restrict__ wkan, const float* __restrict__ d1,
                       const float* __restrict__ d2, const float* __restrict__ d3) {
    int idx = blockIdx.x * blockDim.x + threadIdx.x;      // over NHID * 176
    if (idx >= NHID * (VPITCH / 4)) return;
    int h = idx / (VPITCH / 4);
    int k = (idx % (VPITCH / 4)) * 4;
    size_t base = (size_t)h * KPAD + k;
#pragma unroll
    for (int v = 0; v < 4; v++) {
        const float* w = (v == 0) ? wkan : (v == 1) ? d1 : (v == 2) ? d2 : d3;
        union { __nv_bfloat16 b[4]; uint2 u; } ph, pl;
#pragma unroll
        for (int j = 0; j < 4; j++) {
            float val = (k + j < NIN) ? w[h * NIN + k + j] : 0.f;
            __nv_bfloat16 hh = __float2bfloat16_rn(val);
            ph.b[j] = hh;
            pl.b[j] = __float2bfloat16_rn(val - __bfloat162float(hh));
        }
        *(uint2*)&g_Bhi[base + (size_t)v * VPITCH] = ph.u;
        *(uint2*)&g_Blo[base + (size_t)v * VPITCH] = pl.u;
    }
}

__global__ void prep_wrec(const float* __restrict__ wrec) {
    int idx = blockIdx.x * blockDim.x + threadIdx.x;
    if (idx >= NHID * NHID) return;
    int j = idx / NHID;
    int h = idx - j * NHID;
    g_wrecT[idx] = wrec[h * NHID + j];
}

// ---------------- phase 1: mma.sync bf16x3 GEMM -----------------------------
// C = Ahi Bhi^T + Ahi Blo^T + Alo Bhi^T,  tiles 128x128, KC=32 bf16, 4 stages
#define BM 128
#define BN 128
#define KC 32
#define NCHUNK (KPAD / KC)       // 88
#define PITCHB 80                // bytes per smem row (64 data + 16 pad) -> conflict-free
#define ABYTES (128 * PITCHB)    // 10240 per array
#define O_AHI 0
#define O_ALO ABYTES
#define O_BHI (2 * ABYTES)
#define O_BLO (3 * ABYTES)
#define STAGE (4 * ABYTES)       // 40960
#define NSTG 4
#define SMEM_BYTES (NSTG * STAGE)   // 163840

__device__ __forceinline__ uint32_t smem_u32(const void* p) {
    uint32_t a;
    asm("{ .reg .u64 t; cvta.to.shared.u64 t, %1; cvt.u32.u64 %0, t; }" : "=r"(a) : "l"(p));
    return a;
}
__device__ __forceinline__ void cpa16(uint32_t s, const void* g) {
    asm volatile("cp.async.cg.shared.global [%0], [%1], 16;" :: "r"(s), "l"(g));
}

#define MMA_BF16(C, A, B) \
    asm volatile("mma.sync.aligned.m16n8k16.row.col.f32.bf16.bf16.f32 " \
                 "{%0,%1,%2,%3}, {%4,%5,%6,%7}, {%8,%9}, {%0,%1,%2,%3};" \
                 : "+f"((C)[0]), "+f"((C)[1]), "+f"((C)[2]), "+f"((C)[3]) \
                 : "r"((A)[0]), "r"((A)[1]), "r"((A)[2]), "r"((A)[3]), \
                   "r"((B)[0]), "r"((B)[1]))

__global__ void __launch_bounds__(256, 1) gemm_mma() {
    extern __shared__ char smemc[];
    const uint32_t sb = smem_u32(smemc);
    const int tid = threadIdx.x;
    const int warp = tid >> 5;
    const int lane = tid & 31;
    const int wm = (warp >> 2) * 64;
    const int wn = (warp & 3) * 32;
    const int m0 = blockIdx.y * BM;
    const int n0 = blockIdx.x * BN;

    float acc[4][4][4];
#pragma unroll
    for (int i = 0; i < 4; i++)
#pragma unroll
        for (int j = 0; j < 4; j++)
#pragma unroll
            for (int q = 0; q < 4; q++) acc[i][j][q] = 0.f;

    // copy mapping: per array 512x16B chunks; i = tid + it*256; r=i>>2, c=i&3
    const int cr = tid >> 2;          // row base (advances by 64 per it)
    const int cc = (tid & 3) * 8;     // bf16 offset (16B chunk)

    // ---- load one stage ----
    auto load_stage = [&](int s) {
        uint32_t b = sb + (uint32_t)(s & (NSTG - 1)) * STAGE;
        int kk0 = s * KC;
#pragma unroll
        for (int it = 0; it < 2; it++) {
            int r = cr + it * 64;
            uint32_t so = (uint32_t)(r * PITCHB + cc * 2);
            size_t ga = (size_t)(m0 + r) * KPAD + kk0 + cc;
            size_t gb = (size_t)(n0 + r) * KPAD + kk0 + cc;
            cpa16(b + O_AHI + so, &g_Ahi[ga]);
            cpa16(b + O_ALO + so, &g_Alo[ga]);
            cpa16(b + O_BHI + so, &g_Bhi[gb]);
            cpa16(b + O_BLO + so, &g_Blo[gb]);
        }
        asm volatile("cp.async.commit_group;" ::: "memory");
    };

    load_stage(0);
    load_stage(1);
    load_stage(2);

    const int rA = wm + (lane >> 2);
    const int t  = lane & 3;

    for (int ch = 0; ch < NCHUNK; ch++) {
        if (ch + 3 < NCHUNK) {
            load_stage(ch + 3);
            asm volatile("cp.async.wait_group 3;" ::: "memory");
        } else {
            int rem = NCHUNK - 1 - ch;
            if (rem == 2)      asm volatile("cp.async.wait_group 2;" ::: "memory");
            else if (rem == 1) asm volatile("cp.async.wait_group 1;" ::: "memory");
            else               asm volatile("cp.async.wait_group 0;" ::: "memory");
        }
        __syncthreads();

        const char* Sbase = smemc + (size_t)(ch & (NSTG - 1)) * STAGE;
        const uint32_t* SAhi = (const uint32_t*)(Sbase + O_AHI);
        const uint32_t* SAlo = (const uint32_t*)(Sbase + O_ALO);
        const uint32_t* SBhi = (const uint32_t*)(Sbase + O_BHI);
        const uint32_t* SBlo = (const uint32_t*)(Sbase + O_BLO);

#pragma unroll
        for (int ks = 0; ks < 2; ks++) {
            const int k0w = ks * 8;         // word offset (16 bf16 = 8 words)
            uint32_t ahi[4][4], alo[4][4], bhi[4][2], blo[4][2];
#pragma unroll
            for (int i = 0; i < 4; i++) {
                int r = rA + i * 16;
                int w0 = r * 20 + k0w + t;
                int w1 = (r + 8) * 20 + k0w + t;
                ahi[i][0] = SAhi[w0];
                ahi[i][1] = SAhi[w1];
                ahi[i][2] = SAhi[w0 + 4];
                ahi[i][3] = SAhi[w1 + 4];
                alo[i][0] = SAlo[w0];
                alo[i][1] = SAlo[w1];
                alo[i][2] = SAlo[w0 + 4];
                alo[i][3] = SAlo[w1 + 4];
            }
#pragma unroll
            for (int j = 0; j < 4; j++) {
                int n = wn + j * 8 + (lane >> 2);
                int w0 = n * 20 + k0w + t;
                bhi[j][0] = SBhi[w0];
                bhi[j][1] = SBhi[w0 + 4];
                blo[j][0] = SBlo[w0];
                blo[j][1] = SBlo[w0 + 4];
            }
#pragma unroll
            for (int i = 0; i < 4; i++)
#pragma unroll
                for (int j = 0; j < 4; j++) MMA_BF16(acc[i][j], ahi[i], bhi[j]);
#pragma unroll
            for (int i = 0; i < 4; i++)
#pragma unroll
                for (int j = 0; j < 4; j++) MMA_BF16(acc[i][j], ahi[i], blo[j]);
#pragma unroll
            for (int i = 0; i < 4; i++)
#pragma unroll
                for (int j = 0; j < 4; j++) MMA_BF16(acc[i][j], alo[i], bhi[j]);
        }
        __syncthreads();
    }

    // ---- epilogue: frags -> smem bounce -> coalesced gmem ----
    {
        float* sC = (float*)smemc;             // [128][132]
#pragma unroll
        for (int i = 0; i < 4; i++) {
            int r = wm + i * 16 + (lane >> 2);
#pragma unroll
            for (int j = 0; j < 4; j++) {
                int c = wn + j * 8 + 2 * (lane & 3);
                sC[r * 132 + c]           = acc[i][j][0];
                sC[r * 132 + c + 1]       = acc[i][j][1];
                sC[(r + 8) * 132 + c]     = acc[i][j][2];
                sC[(r + 8) * 132 + c + 1] = acc[i][j][3];
            }
        }
        __syncthreads();
#pragma unroll
        for (int it = 0; it < 16; it++) {
            int i = tid + it * 256;            // 0..4095 float4s
            int r = i >> 5, c4 = (i & 31) * 4;
            float4 v = *(float4*)&sC[r * 132 + c4];
            *(float4*)&g_iin[(size_t)(m0 + r) * NHID + n0 + c4] = v;
        }
    }
}

// ---------------- phase 2: persistent per-batch recurrence ------------------
__global__ void __launch_bounds__(512) snn_seq(const float* __restrict__ wout,
                                               float* __restrict__ out) {
    __shared__ float s_wout[NOUT * NHID];
    __shared__ float s_sf[NHID];
    __shared__ int   s_list[NHID];
    __shared__ int   s_warpcnt[16];
    __shared__ int   s_cnt;
    __shared__ float s_iout[NOUT];

    const int b = blockIdx.x;
    const int h = threadIdx.x;
    const int warp = h >> 5;
    const int lane = h & 31;

    for (int i = h; i < NOUT * NHID; i += 512) s_wout[i] = wout[i];
    s_sf[h] = 0.f;
    if (h == 0) s_cnt = 0;

    float v1 = 0.f, a1 = 0.f, s_prev = 0.f;
    float v_out = 0.f, acc_out = 0.f;

    __syncthreads();

    const float* iin_b = &g_iin[(size_t)b * TSTEPS * NHID];

    for (int t = 0; t < TSTEPS; t++) {
        float rec = 0.f;
        const int cnt = s_cnt;
        int k = 0;
        for (; k + 4 <= cnt; k += 4) {
            int j0 = s_list[k], j1 = s_list[k + 1], j2 = s_list[k + 2], j3 = s_list[k + 3];
            float w0 = g_wrecT[(size_t)j0 * NHID + h];
            float w1 = g_wrecT[(size_t)j1 * NHID + h];
            float w2 = g_wrecT[(size_t)j2 * NHID + h];
            float w3 = g_wrecT[(size_t)j3 * NHID + h];
            rec += w0 + w1 + w2 + w3;
        }
        for (; k < cnt; k++) rec += g_wrecT[(size_t)s_list[k] * NHID + h];

        const float i1 = iin_b[(size_t)t * NHID + h] + rec;

        v1 = 0.95f * v1 + 0.05f * i1 - 1.0f * s_prev;
        a1 = 0.85f * a1 + 0.15f * s_prev;
        const float thr = 1.0f + 0.05f * a1;
        const float s_new = (v1 > thr) ? 1.f : 0.f;

        const unsigned mask = __ballot_sync(0xffffffffu, s_new > 0.f);

        __syncthreads();

        if (lane == 0) s_warpcnt[warp] = __popc(mask);
        s_sf[h] = s_new;

        __syncthreads();

        int base = 0;
#pragma unroll
        for (int w = 0; w < 16; w++) base += (w < warp) ? s_warpcnt[w] : 0;
        if (s_new > 0.f) {
            int pos = base + __popc(mask & ((1u << lane) - 1u));
            s_list[pos] = h;
        }
        if (h == 0) {
            int tot = 0;
#pragma unroll
            for (int w = 0; w < 16; w++) tot += s_warpcnt[w];
            s_cnt = tot;
        }

        for (int o = warp; o < NOUT; o += 16) {
            float p = 0.f;
            const float* wrow = &s_wout[o * NHID];
#pragma unroll 4
            for (int i = lane; i < NHID; i += 32) p += s_sf[i] * wrow[i];
#pragma unroll
            for (int off = 16; off > 0; off >>= 1)
                p += __shfl_down_sync(0xffffffffu, p, off);
            if (lane == 0) s_iout[o] = p;
        }

        __syncthreads();

        if (h < NOUT) {
            v_out = 0.9f * v_out + s_iout[h];
            const float s_o = (v_out > 1.0f) ? 1.f : 0.f;
            v_out = v_out - 1.0f * s_o;
            acc_out += v_out;
        }

        s_prev = s_new;
    }

    if (h < NOUT) out[b * NOUT + h] = acc_out * (1.0f / (float)TSTEPS);
}

// ---------------- launch -----------------------------------------------------
extern "C" void kernel_launch(void* const* d_in, const int* in_sizes, int n_in,
                              void* d_out, int out_size) {
    const float* x    = (const float*)d_in[0];
    const float* wkan = (const float*)d_in[1];
    const float* d1   = (const float*)d_in[2];
    const float* d2   = (const float*)d_in[3];
    const float* d3   = (const float*)d_in[4];
    const float* wrec = (const float*)d_in[5];
    const float* wout = (const float*)d_in[6];
    float* out = (float*)d_out;

    cudaFuncSetAttribute(gemm_mma, cudaFuncAttributeMaxDynamicSharedMemorySize, SMEM_BYTES);

    prep_A<<<(MROWS * (VPITCH / 4) + 255) / 256, 256>>>(x);
    prep_B<<<(NHID * (VPITCH / 4) + 255) / 256, 256>>>(wkan, d1, d2, d3);
    prep_wrec<<<(NHID * NHID + 255) / 256, 256>>>(wrec);

    dim3 grid(NHID / BN, MROWS / BM);   // (4, 500)
    gemm_mma<<<grid, 256, SMEM_BYTES>>>();

    snn_seq<<<BATCH, 512>>>(wout, out);
}

// round 9
// speedup vs baseline: 2.7027x; 1.0951x over previous
#include <cuda_runtime.h>
#include <cuda_bf16.h>
#include <cstdint>

#define BATCH 256
#define TSTEPS 250
#define NIN 700
#define NHID 512
#define NOUT 20
#define VPITCH 704            // per-variant padded K
#define KPAD (4*VPITCH)       // 2816
#define MROWS (BATCH*TSTEPS)  // 64000

// ---------------- device scratch (no allocations allowed) -------------------
__device__ float g_iin[(size_t)MROWS * NHID];
__device__ float g_wrecT[(size_t)NHID * NHID];
__device__ __nv_bfloat16 g_Ahi[(size_t)MROWS * KPAD];
__device__ __nv_bfloat16 g_Alo[(size_t)MROWS * KPAD];
__device__ __nv_bfloat16 g_Bhi[(size_t)NHID * KPAD];
__device__ __nv_bfloat16 g_Blo[(size_t)NHID * KPAD];

// ---------------- prep kernels ----------------------------------------------
__global__ void prep_A(const float* __restrict__ x) {
    int idx = blockIdx.x * blockDim.x + threadIdx.x;      // over MROWS * 176
    if (idx >= MROWS * (VPITCH / 4)) return;
    int m = idx / (VPITCH / 4);
    int k = (idx % (VPITCH / 4)) * 4;
    const float* xr = x + (size_t)m * NIN;
    float a[4];
#pragma unroll
    for (int j = 0; j < 4; j++) a[j] = (k + j < NIN) ? xr[k + j] : 0.f;

    size_t base = (size_t)m * KPAD + k;
#pragma unroll
    for (int v = 0; v < 4; v++) {
        union { __nv_bfloat16 b[4]; uint2 u; } ph, pl;
#pragma unroll
        for (int j = 0; j < 4; j++) {
            float t1 = fminf(fabsf(a[j]), 1.f);
            float val = (v == 0) ? a[j] : (v == 1) ? t1 : (v == 2) ? t1 * t1 : t1 * t1 * t1;
            __nv_bfloat16 h = __float2bfloat16_rn(val);
            ph.b[j] = h;
            pl.b[j] = __float2bfloat16_rn(val - __bfloat162float(h));
        }
        *(uint2*)&g_Ahi[base + (size_t)v * VPITCH] = ph.u;
        *(uint2*)&g_Alo[base + (size_t)v * VPITCH] = pl.u;
    }
}

__global__ void prep_B(const float* __restrict__ wkan, const float* __restrict__ d1,
                       const float* __restrict__ d2, const float* __restrict__ d3) {
    int idx = blockIdx.x * blockDim.x + threadIdx.x;      // over NHID * 176
    if (idx >= NHID * (VPITCH / 4)) return;
    int h = idx / (VPITCH / 4);
    int k = (idx % (VPITCH / 4)) * 4;
    size_t base = (size_t)h * KPAD + k;
#pragma unroll
    for (int v = 0; v < 4; v++) {
        const float* w = (v == 0) ? wkan : (v == 1) ? d1 : (v == 2) ? d2 : d3;
        union { __nv_bfloat16 b[4]; uint2 u; } ph, pl;
#pragma unroll
        for (int j = 0; j < 4; j++) {
            float val = (k + j < NIN) ? w[h * NIN + k + j] : 0.f;
            __nv_bfloat16 hh = __float2bfloat16_rn(val);
            ph.b[j] = hh;
            pl.b[j] = __float2bfloat16_rn(val - __bfloat162float(hh));
        }
        *(uint2*)&g_Bhi[base + (size_t)v * VPITCH] = ph.u;
        *(uint2*)&g_Blo[base + (size_t)v * VPITCH] = pl.u;
    }
}

__global__ void prep_wrec(const float* __restrict__ wrec) {
    int idx = blockIdx.x * blockDim.x + threadIdx.x;
    if (idx >= NHID * NHID) return;
    int j = idx / NHID;
    int h = idx - j * NHID;
    g_wrecT[idx] = wrec[h * NHID + j];
}

// ---------------- phase 1: mma.sync bf16x3 GEMM -----------------------------
// C = Ahi Bhi^T + Ahi Blo^T + Alo Bhi^T,  tiles 128x128, KC=32 bf16,
// 2 stages x 40KB = 80KB smem -> 2 CTAs per SM.
#define BM 128
#define BN 128
#define KC 32
#define NCHUNK (KPAD / KC)       // 88
#define PITCHB 80                // bytes per smem row (64 data + 16 pad)
#define ABYTES (128 * PITCHB)    // 10240 per array
#define O_AHI 0
#define O_ALO ABYTES
#define O_BHI (2 * ABYTES)
#define O_BLO (3 * ABYTES)
#define STAGE (4 * ABYTES)       // 40960
#define NSTG 2
#define SMEM_BYTES (NSTG * STAGE)   // 81920

__device__ __forceinline__ uint32_t smem_u32(const void* p) {
    uint32_t a;
    asm("{ .reg .u64 t; cvta.to.shared.u64 t, %1; cvt.u32.u64 %0, t; }" : "=r"(a) : "l"(p));
    return a;
}
__device__ __forceinline__ void cpa16(uint32_t s, const void* g) {
    asm volatile("cp.async.cg.shared.global [%0], [%1], 16;" :: "r"(s), "l"(g));
}

#define MMA_BF16(C, A, B) \
    asm volatile("mma.sync.aligned.m16n8k16.row.col.f32.bf16.bf16.f32 " \
                 "{%0,%1,%2,%3}, {%4,%5,%6,%7}, {%8,%9}, {%0,%1,%2,%3};" \
                 : "+f"((C)[0]), "+f"((C)[1]), "+f"((C)[2]), "+f"((C)[3]) \
                 : "r"((A)[0]), "r"((A)[1]), "r"((A)[2]), "r"((A)[3]), \
                   "r"((B)[0]), "r"((B)[1]))

__global__ void __launch_bounds__(256, 2) gemm_mma() {
    extern __shared__ char smemc[];
    const uint32_t sb = smem_u32(smemc);
    const int tid = threadIdx.x;
    const int warp = tid >> 5;
    const int lane = tid & 31;
    const int wm = (warp >> 2) * 64;
    const int wn = (warp & 3) * 32;
    const int m0 = blockIdx.y * BM;
    const int n0 = blockIdx.x * BN;

    float acc[4][4][4];
#pragma unroll
    for (int i = 0; i < 4; i++)
#pragma unroll
        for (int j = 0; j < 4; j++)
#pragma unroll
            for (int q = 0; q < 4; q++) acc[i][j][q] = 0.f;

    // copy mapping: per array 512x16B chunks; i = tid + it*256; r=i>>2, c=i&3
    const int cr = tid >> 2;          // row base (advances by 64 per it)
    const int cc = (tid & 3) * 8;     // bf16 offset (16B chunk)

    auto load_stage = [&](int s) {
        uint32_t b = sb + (uint32_t)(s & (NSTG - 1)) * STAGE;
        int kk0 = s * KC;
#pragma unroll
        for (int it = 0; it < 2; it++) {
            int r = cr + it * 64;
            uint32_t so = (uint32_t)(r * PITCHB + cc * 2);
            size_t ga = (size_t)(m0 + r) * KPAD + kk0 + cc;
            size_t gb = (size_t)(n0 + r) * KPAD + kk0 + cc;
            cpa16(b + O_AHI + so, &g_Ahi[ga]);
            cpa16(b + O_ALO + so, &g_Alo[ga]);
            cpa16(b + O_BHI + so, &g_Bhi[gb]);
            cpa16(b + O_BLO + so, &g_Blo[gb]);
        }
        asm volatile("cp.async.commit_group;" ::: "memory");
    };

    load_stage(0);

    const int rA = wm + (lane >> 2);
    const int t  = lane & 3;

    for (int ch = 0; ch < NCHUNK; ch++) {
        if (ch + 1 < NCHUNK) {
            load_stage(ch + 1);
            asm volatile("cp.async.wait_group 1;" ::: "memory");
        } else {
            asm volatile("cp.async.wait_group 0;" ::: "memory");
        }
        __syncthreads();

        const char* Sbase = smemc + (size_t)(ch & (NSTG - 1)) * STAGE;
        const uint32_t* SAhi = (const uint32_t*)(Sbase + O_AHI);
        const uint32_t* SAlo = (const uint32_t*)(Sbase + O_ALO);
        const uint32_t* SBhi = (const uint32_t*)(Sbase + O_BHI);
        const uint32_t* SBlo = (const uint32_t*)(Sbase + O_BLO);

#pragma unroll
        for (int ks = 0; ks < 2; ks++) {
            const int k0w = ks * 8;         // word offset (16 bf16 = 8 words)
            uint32_t af[4][4], bh[4][2], bl[4][2];
            // ---- pass 1: ahi, bhi ----
#pragma unroll
            for (int i = 0; i < 4; i++) {
                int r = rA + i * 16;
                int w0 = r * 20 + k0w + t;
                int w1 = (r + 8) * 20 + k0w + t;
                af[i][0] = SAhi[w0];
                af[i][1] = SAhi[w1];
                af[i][2] = SAhi[w0 + 4];
                af[i][3] = SAhi[w1 + 4];
            }
#pragma unroll
            for (int j = 0; j < 4; j++) {
                int n = wn + j * 8 + (lane >> 2);
                int w0 = n * 20 + k0w + t;
                bh[j][0] = SBhi[w0];
                bh[j][1] = SBhi[w0 + 4];
                bl[j][0] = SBlo[w0];
                bl[j][1] = SBlo[w0 + 4];
            }
#pragma unroll
            for (int i = 0; i < 4; i++)
#pragma unroll
                for (int j = 0; j < 4; j++) MMA_BF16(acc[i][j], af[i], bh[j]);
            // ---- pass 2: ahi, blo ----
#pragma unroll
            for (int i = 0; i < 4; i++)
#pragma unroll
                for (int j = 0; j < 4; j++) MMA_BF16(acc[i][j], af[i], bl[j]);
            // ---- pass 3: alo (reuse af regs), bhi ----
#pragma unroll
            for (int i = 0; i < 4; i++) {
                int r = rA + i * 16;
                int w0 = r * 20 + k0w + t;
                int w1 = (r + 8) * 20 + k0w + t;
                af[i][0] = SAlo[w0];
                af[i][1] = SAlo[w1];
                af[i][2] = SAlo[w0 + 4];
                af[i][3] = SAlo[w1 + 4];
            }
#pragma unroll
            for (int i = 0; i < 4; i++)
#pragma unroll
                for (int j = 0; j < 4; j++) MMA_BF16(acc[i][j], af[i], bh[j]);
        }
        __syncthreads();
    }

    // ---- epilogue: frags -> smem bounce -> coalesced gmem ----
    {
        float* sC = (float*)smemc;             // [128][132] = 67.6KB <= 80KB
#pragma unroll
        for (int i = 0; i < 4; i++) {
            int r = wm + i * 16 + (lane >> 2);
#pragma unroll
            for (int j = 0; j < 4; j++) {
                int c = wn + j * 8 + 2 * (lane & 3);
                sC[r * 132 + c]           = acc[i][j][0];
                sC[r * 132 + c + 1]       = acc[i][j][1];
                sC[(r + 8) * 132 + c]     = acc[i][j][2];
                sC[(r + 8) * 132 + c + 1] = acc[i][j][3];
            }
        }
        __syncthreads();
#pragma unroll
        for (int it = 0; it < 16; it++) {
            int i = tid + it * 256;            // 0..4095 float4s
            int r = i >> 5, c4 = (i & 31) * 4;
            float4 v = *(float4*)&sC[r * 132 + c4];
            *(float4*)&g_iin[(size_t)(m0 + r) * NHID + n0 + c4] = v;
        }
    }
}

// ---------------- phase 2: persistent per-batch recurrence ------------------
__global__ void __launch_bounds__(512) snn_seq(const float* __restrict__ wout,
                                               float* __restrict__ out) {
    __shared__ float s_wout[NOUT * NHID];
    __shared__ float s_sf[NHID];
    __shared__ int   s_list[NHID];
    __shared__ int   s_warpcnt[16];
    __shared__ int   s_cnt;
    __shared__ float s_iout[NOUT];

    const int b = blockIdx.x;
    const int h = threadIdx.x;
    const int warp = h >> 5;
    const int lane = h & 31;

    for (int i = h; i < NOUT * NHID; i += 512) s_wout[i] = wout[i];
    s_sf[h] = 0.f;
    if (h == 0) s_cnt = 0;

    float v1 = 0.f, a1 = 0.f, s_prev = 0.f;
    float v_out = 0.f, acc_out = 0.f;

    __syncthreads();

    const float* iin_b = &g_iin[(size_t)b * TSTEPS * NHID];

    for (int t = 0; t < TSTEPS; t++) {
        float rec = 0.f;
        const int cnt = s_cnt;
        int k = 0;
        for (; k + 4 <= cnt; k += 4) {
            int j0 = s_list[k], j1 = s_list[k + 1], j2 = s_list[k + 2], j3 = s_list[k + 3];
            float w0 = g_wrecT[(size_t)j0 * NHID + h];
            float w1 = g_wrecT[(size_t)j1 * NHID + h];
            float w2 = g_wrecT[(size_t)j2 * NHID + h];
            float w3 = g_wrecT[(size_t)j3 * NHID + h];
            rec += w0 + w1 + w2 + w3;
        }
        for (; k < cnt; k++) rec += g_wrecT[(size_t)s_list[k] * NHID + h];

        const float i1 = iin_b[(size_t)t * NHID + h] + rec;

        v1 = 0.95f * v1 + 0.05f * i1 - 1.0f * s_prev;
        a1 = 0.85f * a1 + 0.15f * s_prev;
        const float thr = 1.0f + 0.05f * a1;
        const float s_new = (v1 > thr) ? 1.f : 0.f;

        const unsigned mask = __ballot_sync(0xffffffffu, s_new > 0.f);

        __syncthreads();

        if (lane == 0) s_warpcnt[warp] = __popc(mask);
        s_sf[h] = s_new;

        __syncthreads();

        int base = 0;
#pragma unroll
        for (int w = 0; w < 16; w++) base += (w < warp) ? s_warpcnt[w] : 0;
        if (s_new > 0.f) {
            int pos = base + __popc(mask & ((1u << lane) - 1u));
            s_list[pos] = h;
        }
        if (h == 0) {
            int tot = 0;
#pragma unroll
            for (int w = 0; w < 16; w++) tot += s_warpcnt[w];
            s_cnt = tot;
        }

        for (int o = warp; o < NOUT; o += 16) {
            float p = 0.f;
            const float* wrow = &s_wout[o * NHID];
#pragma unroll 4
            for (int i = lane; i < NHID; i += 32) p += s_sf[i] * wrow[i];
#pragma unroll
            for (int off = 16; off > 0; off >>= 1)
                p += __shfl_down_sync(0xffffffffu, p, off);
            if (lane == 0) s_iout[o] = p;
        }

        __syncthreads();

        if (h < NOUT) {
            v_out = 0.9f * v_out + s_iout[h];
            const float s_o = (v_out > 1.0f) ? 1.f : 0.f;
            v_out = v_out - 1.0f * s_o;
            acc_out += v_out;
        }

        s_prev = s_new;
    }

    if (h < NOUT) out[b * NOUT + h] = acc_out * (1.0f / (float)TSTEPS);
}

// ---------------- launch -----------------------------------------------------
extern "C" void kernel_launch(void* const* d_in, const int* in_sizes, int n_in,
                              void* d_out, int out_size) {
    const float* x    = (const float*)d_in[0];
    const float* wkan = (const float*)d_in[1];
    const float* d1   = (const float*)d_in[2];
    const float* d2   = (const float*)d_in[3];
    const float* d3   = (const float*)d_in[4];
    const float* wrec = (const float*)d_in[5];
    const float* wout = (const float*)d_in[6];
    float* out = (float*)d_out;

    cudaFuncSetAttribute(gemm_mma, cudaFuncAttributeMaxDynamicSharedMemorySize, SMEM_BYTES);

    prep_A<<<(MROWS * (VPITCH / 4) + 255) / 256, 256>>>(x);
    prep_B<<<(NHID * (VPITCH / 4) + 255) / 256, 256>>>(wkan, d1, d2, d3);
    prep_wrec<<<(NHID * NHID + 255) / 256, 256>>>(wrec);

    dim3 grid(NHID / BN, MROWS / BM);   // (4, 500)
    gemm_mma<<<grid, 256, SMEM_BYTES>>>();

    snn_seq<<<BATCH, 512>>>(wout, out);
}

// round 10
// speedup vs baseline: 2.8423x; 1.0517x over previous
#include <cuda_runtime.h>
#include <cuda_bf16.h>
#include <cstdint>

#define BATCH 256
#define TSTEPS 250
#define NIN 700
#define NHID 512
#define NOUT 20
#define VPITCH 704            // per-variant padded K
#define KPAD (4*VPITCH)       // 2816
#define MROWS (BATCH*TSTEPS)  // 64000

// ---------------- device scratch (no allocations allowed) -------------------
__device__ float g_iin[(size_t)MROWS * NHID];
__device__ float g_wrecT[(size_t)NHID * NHID];
__device__ __nv_bfloat16 g_Ahi[(size_t)MROWS * KPAD];
__device__ __nv_bfloat16 g_Alo[(size_t)MROWS * KPAD];
__device__ __nv_bfloat16 g_Bhi[(size_t)NHID * KPAD];
__device__ __nv_bfloat16 g_Blo[(size_t)NHID * KPAD];

// ---------------- prep kernels ----------------------------------------------
__global__ void prep_A(const float* __restrict__ x) {
    int idx = blockIdx.x * blockDim.x + threadIdx.x;      // over MROWS * 176
    if (idx >= MROWS * (VPITCH / 4)) return;
    int m = idx / (VPITCH / 4);
    int k = (idx % (VPITCH / 4)) * 4;
    const float* xr = x + (size_t)m * NIN;
    float a[4];
#pragma unroll
    for (int j = 0; j < 4; j++) a[j] = (k + j < NIN) ? xr[k + j] : 0.f;

    size_t base = (size_t)m * KPAD + k;
#pragma unroll
    for (int v = 0; v < 4; v++) {
        union { __nv_bfloat16 b[4]; uint2 u; } ph, pl;
#pragma unroll
        for (int j = 0; j < 4; j++) {
            float t1 = fminf(fabsf(a[j]), 1.f);
            float val = (v == 0) ? a[j] : (v == 1) ? t1 : (v == 2) ? t1 * t1 : t1 * t1 * t1;
            __nv_bfloat16 h = __float2bfloat16_rn(val);
            ph.b[j] = h;
            pl.b[j] = __float2bfloat16_rn(val - __bfloat162float(h));
        }
        *(uint2*)&g_Ahi[base + (size_t)v * VPITCH] = ph.u;
        *(uint2*)&g_Alo[base + (size_t)v * VPITCH] = pl.u;
    }
}

__global__ void prep_B(const float* __restrict__ wkan, const float* __restrict__ d1,
                       const float* __restrict__ d2, const float* __restrict__ d3) {
    int idx = blockIdx.x * blockDim.x + threadIdx.x;      // over NHID * 176
    if (idx >= NHID * (VPITCH / 4)) return;
    int h = idx / (VPITCH / 4);
    int k = (idx % (VPITCH / 4)) * 4;
    size_t base = (size_t)h * KPAD + k;
#pragma unroll
    for (int v = 0; v < 4; v++) {
        const float* w = (v == 0) ? wkan : (v == 1) ? d1 : (v == 2) ? d2 : d3;
        union { __nv_bfloat16 b[4]; uint2 u; } ph, pl;
#pragma unroll
        for (int j = 0; j < 4; j++) {
            float val = (k + j < NIN) ? w[h * NIN + k + j] : 0.f;
            __nv_bfloat16 hh = __float2bfloat16_rn(val);
            ph.b[j] = hh;
            pl.b[j] = __float2bfloat16_rn(val - __bfloat162float(hh));
        }
        *(uint2*)&g_Bhi[base + (size_t)v * VPITCH] = ph.u;
        *(uint2*)&g_Blo[base + (size_t)v * VPITCH] = pl.u;
    }
}

__global__ void prep_wrec(const float* __restrict__ wrec) {
    int idx = blockIdx.x * blockDim.x + threadIdx.x;
    if (idx >= NHID * NHID) return;
    int j = idx / NHID;
    int h = idx - j * NHID;
    g_wrecT[idx] = wrec[h * NHID + j];
}

// ---------------- phase 1: mma.sync bf16x3 GEMM (ldmatrix frags) ------------
#define BM 128
#define BN 128
#define KC 32
#define NCHUNK (KPAD / KC)       // 88
#define PITCHB 80                // bytes per smem row (conflict-free mod 128)
#define ABYTES (128 * PITCHB)    // 10240 per array
#define O_AHI 0
#define O_ALO ABYTES
#define O_BHI (2 * ABYTES)
#define O_BLO (3 * ABYTES)
#define STAGE (4 * ABYTES)       // 40960
#define NSTG 2
#define SMEM_BYTES (NSTG * STAGE)   // 81920

__device__ __forceinline__ uint32_t smem_u32(const void* p) {
    uint32_t a;
    asm("{ .reg .u64 t; cvta.to.shared.u64 t, %1; cvt.u32.u64 %0, t; }" : "=r"(a) : "l"(p));
    return a;
}
__device__ __forceinline__ void cpa16(uint32_t s, const void* g) {
    asm volatile("cp.async.cg.shared.global [%0], [%1], 16;" :: "r"(s), "l"(g));
}

#define MMA_BF16(C, A, B) \
    asm volatile("mma.sync.aligned.m16n8k16.row.col.f32.bf16.bf16.f32 " \
                 "{%0,%1,%2,%3}, {%4,%5,%6,%7}, {%8,%9}, {%0,%1,%2,%3};" \
                 : "+f"((C)[0]), "+f"((C)[1]), "+f"((C)[2]), "+f"((C)[3]) \
                 : "r"((A)[0]), "r"((A)[1]), "r"((A)[2]), "r"((A)[3]), \
                   "r"((B)[0]), "r"((B)[1]))

#define LDMX4(r0, r1, r2, r3, addr) \
    asm volatile("ldmatrix.sync.aligned.m8n8.x4.shared.b16 {%0,%1,%2,%3}, [%4];" \
                 : "=r"(r0), "=r"(r1), "=r"(r2), "=r"(r3) : "r"(addr))

__global__ void __launch_bounds__(256, 2) gemm_mma() {
    extern __shared__ char smemc[];
    const uint32_t sb = smem_u32(smemc);
    const int tid = threadIdx.x;
    const int warp = tid >> 5;
    const int lane = tid & 31;
    const int wm = (warp >> 2) * 64;
    const int wn = (warp & 3) * 32;
    const int m0 = blockIdx.y * BM;
    const int n0 = blockIdx.x * BN;

    float acc[4][4][4];
#pragma unroll
    for (int i = 0; i < 4; i++)
#pragma unroll
        for (int j = 0; j < 4; j++)
#pragma unroll
            for (int q = 0; q < 4; q++) acc[i][j][q] = 0.f;

    // ldmatrix per-lane base offsets (bytes within one array):
    // A x4: matrices {rows+0 k0, rows+8 k0, rows+0 k8, rows+8 k8}
    const uint32_t a_base =
        (uint32_t)(wm + ((lane >> 3) & 1) * 8 + (lane & 7)) * PITCHB + (lane >> 4) * 16;
    // B x4 for j-pair: matrices {nj k0, nj k8, nj+8 k0, nj+8 k8}
    const uint32_t b_base =
        (uint32_t)(wn + ((lane >> 4) & 1) * 8 + (lane & 7)) * PITCHB + ((lane >> 3) & 1) * 16;

    // cp.async copy mapping
    const int cr = tid >> 2;
    const int cc = (tid & 3) * 8;

    auto load_stage = [&](int s) {
        uint32_t b = sb + (uint32_t)(s & (NSTG - 1)) * STAGE;
        int kk0 = s * KC;
#pragma unroll
        for (int it = 0; it < 2; it++) {
            int r = cr + it * 64;
            uint32_t so = (uint32_t)(r * PITCHB + cc * 2);
            size_t ga = (size_t)(m0 + r) * KPAD + kk0 + cc;
            size_t gb = (size_t)(n0 + r) * KPAD + kk0 + cc;
            cpa16(b + O_AHI + so, &g_Ahi[ga]);
            cpa16(b + O_ALO + so, &g_Alo[ga]);
            cpa16(b + O_BHI + so, &g_Bhi[gb]);
            cpa16(b + O_BLO + so, &g_Blo[gb]);
        }
        asm volatile("cp.async.commit_group;" ::: "memory");
    };

    load_stage(0);

    for (int ch = 0; ch < NCHUNK; ch++) {
        if (ch + 1 < NCHUNK) {
            load_stage(ch + 1);
            asm volatile("cp.async.wait_group 1;" ::: "memory");
        } else {
            asm volatile("cp.async.wait_group 0;" ::: "memory");
        }
        __syncthreads();

        const uint32_t Sb = sb + (uint32_t)(ch & (NSTG - 1)) * STAGE;

#pragma unroll
        for (int ks = 0; ks < 2; ks++) {
            const uint32_t ko = ks * 32;          // byte offset for this k-step
            uint32_t af[4][4], bh[4][2], bl[4][2];

            // B frags: 2 ldmatrix for hi, 2 for lo (each covers a j-pair)
            LDMX4(bh[0][0], bh[0][1], bh[1][0], bh[1][1], Sb + O_BHI + b_base + ko);
            LDMX4(bh[2][0], bh[2][1], bh[3][0], bh[3][1], Sb + O_BHI + b_base + 16 * PITCHB + ko);
            LDMX4(bl[0][0], bl[0][1], bl[1][0], bl[1][1], Sb + O_BLO + b_base + ko);
            LDMX4(bl[2][0], bl[2][1], bl[3][0], bl[3][1], Sb + O_BLO + b_base + 16 * PITCHB + ko);

            // ---- pass 1: ahi x bhi ----
#pragma unroll
            for (int i = 0; i < 4; i++)
                LDMX4(af[i][0], af[i][1], af[i][2], af[i][3],
                      Sb + O_AHI + a_base + (uint32_t)i * 16 * PITCHB + ko);
#pragma unroll
            for (int i = 0; i < 4; i++)
#pragma unroll
                for (int j = 0; j < 4; j++) MMA_BF16(acc[i][j], af[i], bh[j]);
            // ---- pass 2: ahi x blo ----
#pragma unroll
            for (int i = 0; i < 4; i++)
#pragma unroll
                for (int j = 0; j < 4; j++) MMA_BF16(acc[i][j], af[i], bl[j]);
            // ---- pass 3: alo x bhi (reuse af regs) ----
#pragma unroll
            for (int i = 0; i < 4; i++)
                LDMX4(af[i][0], af[i][1], af[i][2], af[i][3],
                      Sb + O_ALO + a_base + (uint32_t)i * 16 * PITCHB + ko);
#pragma unroll
            for (int i = 0; i < 4; i++)
#pragma unroll
                for (int j = 0; j < 4; j++) MMA_BF16(acc[i][j], af[i], bh[j]);
        }
        __syncthreads();
    }

    // ---- epilogue: frags -> smem bounce -> coalesced gmem ----
    {
        float* sC = (float*)smemc;             // [128][132]
#pragma unroll
        for (int i = 0; i < 4; i++) {
            int r = wm + i * 16 + (lane >> 2);
#pragma unroll
            for (int j = 0; j < 4; j++) {
                int c = wn + j * 8 + 2 * (lane & 3);
                sC[r * 132 + c]           = acc[i][j][0];
                sC[r * 132 + c + 1]       = acc[i][j][1];
                sC[(r + 8) * 132 + c]     = acc[i][j][2];
                sC[(r + 8) * 132 + c + 1] = acc[i][j][3];
            }
        }
        __syncthreads();
#pragma unroll
        for (int it = 0; it < 16; it++) {
            int i = tid + it * 256;            // 0..4095 float4s
            int r = i >> 5, c4 = (i & 31) * 4;
            float4 v = *(float4*)&sC[r * 132 + c4];
            *(float4*)&g_iin[(size_t)(m0 + r) * NHID + n0 + c4] = v;
        }
    }
}

// ---------------- phase 2: persistent per-batch recurrence ------------------
__global__ void __launch_bounds__(512) snn_seq(const float* __restrict__ wout,
                                               float* __restrict__ out) {
    __shared__ float s_wout[NOUT * NHID];
    __shared__ float s_sf[NHID];
    __shared__ int   s_list[NHID];
    __shared__ int   s_warpcnt[16];
    __shared__ int   s_cnt;
    __shared__ float s_iout[NOUT];

    const int b = blockIdx.x;
    const int h = threadIdx.x;
    const int warp = h >> 5;
    const int lane = h & 31;

    for (int i = h; i < NOUT * NHID; i += 512) s_wout[i] = wout[i];
    s_sf[h] = 0.f;
    if (h == 0) s_cnt = 0;

    float v1 = 0.f, a1 = 0.f, s_prev = 0.f;
    float v_out = 0.f, acc_out = 0.f;

    __syncthreads();

    const float* iin_b = &g_iin[(size_t)b * TSTEPS * NHID];

    for (int t = 0; t < TSTEPS; t++) {
        float rec = 0.f;
        const int cnt = s_cnt;
        int k = 0;
        for (; k + 4 <= cnt; k += 4) {
            int j0 = s_list[k], j1 = s_list[k + 1], j2 = s_list[k + 2], j3 = s_list[k + 3];
            float w0 = g_wrecT[(size_t)j0 * NHID + h];
            float w1 = g_wrecT[(size_t)j1 * NHID + h];
            float w2 = g_wrecT[(size_t)j2 * NHID + h];
            float w3 = g_wrecT[(size_t)j3 * NHID + h];
            rec += w0 + w1 + w2 + w3;
        }
        for (; k < cnt; k++) rec += g_wrecT[(size_t)s_list[k] * NHID + h];

        const float i1 = iin_b[(size_t)t * NHID + h] + rec;

        v1 = 0.95f * v1 + 0.05f * i1 - 1.0f * s_prev;
        a1 = 0.85f * a1 + 0.15f * s_prev;
        const float thr = 1.0f + 0.05f * a1;
        const float s_new = (v1 > thr) ? 1.f : 0.f;

        const unsigned mask = __ballot_sync(0xffffffffu, s_new > 0.f);

        __syncthreads();

        if (lane == 0) s_warpcnt[warp] = __popc(mask);
        s_sf[h] = s_new;

        __syncthreads();

        int base = 0;
#pragma unroll
        for (int w = 0; w < 16; w++) base += (w < warp) ? s_warpcnt[w] : 0;
        if (s_new > 0.f) {
            int pos = base + __popc(mask & ((1u << lane) - 1u));
            s_list[pos] = h;
        }
        if (h == 0) {
            int tot = 0;
#pragma unroll
            for (int w = 0; w < 16; w++) tot += s_warpcnt[w];
            s_cnt = tot;
        }

        for (int o = warp; o < NOUT; o += 16) {
            float p = 0.f;
            const float* wrow = &s_wout[o * NHID];
#pragma unroll 4
            for (int i = lane; i < NHID; i += 32) p += s_sf[i] * wrow[i];
#pragma unroll
            for (int off = 16; off > 0; off >>= 1)
                p += __shfl_down_sync(0xffffffffu, p, off);
            if (lane == 0) s_iout[o] = p;
        }

        __syncthreads();

        if (h < NOUT) {
            v_out = 0.9f * v_out + s_iout[h];
            const float s_o = (v_out > 1.0f) ? 1.f : 0.f;
            v_out = v_out - 1.0f * s_o;
            acc_out += v_out;
        }

        s_prev = s_new;
    }

    if (h < NOUT) out[b * NOUT + h] = acc_out * (1.0f / (float)TSTEPS);
}

// ---------------- launch -----------------------------------------------------
extern "C" void kernel_launch(void* const* d_in, const int* in_sizes, int n_in,
                              void* d_out, int out_size) {
    const float* x    = (const float*)d_in[0];
    const float* wkan = (const float*)d_in[1];
    const float* d1   = (const float*)d_in[2];
    const float* d2   = (const float*)d_in[3];
    const float* d3   = (const float*)d_in[4];
    const float* wrec = (const float*)d_in[5];
    const float* wout = (const float*)d_in[6];
    float* out = (float*)d_out;

    cudaFuncSetAttribute(gemm_mma, cudaFuncAttributeMaxDynamicSharedMemorySize, SMEM_BYTES);

    prep_A<<<(MROWS * (VPITCH / 4) + 255) / 256, 256>>>(x);
    prep_B<<<(NHID * (VPITCH / 4) + 255) / 256, 256>>>(wkan, d1, d2, d3);
    prep_wrec<<<(NHID * NHID + 255) / 256, 256>>>(wrec);

    dim3 grid(NHID / BN, MROWS / BM);   // (4, 500)
    gemm_mma<<<grid, 256, SMEM_BYTES>>>();

    snn_seq<<<BATCH, 512>>>(wout, out);
}